// round 1
// baseline (speedup 1.0000x reference)
#include <cuda_runtime.h>

#define NA 50000
#define MN 12
#define NR (NA*MN)          // 600000
#define NCRY 5000
#define ORIGF 200
#define NBRF 64
#define AFL 64
#define EPS 1e-5f

// ---------------- scratch (__device__ globals; no allocation) ----------------
__device__ float g_atom[NA*AFL];            // 12.8 MB
__device__ float g_S[NA*128];               // 25.6 MB (self part + bias)
__device__ float g_T[NA*128];               // 25.6 MB (nbr part, gathered via idx)
__device__ float g_Z[(size_t)NR*128];       // 307 MB pre-BN messages
__device__ float g_psum[12500*128];
__device__ float g_psq [12500*128];
__device__ float g_r2s[125*128];
__device__ float g_r2q[125*128];
__device__ float g_A2[128];
__device__ float g_B2[128];
__device__ float g_summed[NA*AFL];
__device__ float g_p1s[6250*64];
__device__ float g_p1q[6250*64];
__device__ float g_r1s[125*64];
__device__ float g_r1q[125*64];
__device__ float g_A1[64];
__device__ float g_B1[64];
__device__ int   g_idx[NR];
__device__ int   g_flag;

// ---------------- FMA-pipe transcendentals (avoid MUFU bottleneck) ----------
__device__ __forceinline__ float fexp_(float x){
    x = fminf(fmaxf(x, -87.0f), 87.0f);
    float t  = x * 1.4426950408889634f;
    float k  = t + 12582912.0f;              // round-to-nearest trick
    float fi = k - 12582912.0f;
    float f  = t - fi;                       // f in [-0.5, 0.5]
    int   e  = __float_as_int(k) - 0x4B400000;
    float p  = 1.5403530393e-4f;
    p = fmaf(p, f, 1.3333558146e-3f);
    p = fmaf(p, f, 9.6181291918e-3f);
    p = fmaf(p, f, 5.5504108665e-2f);
    p = fmaf(p, f, 2.4022650696e-1f);
    p = fmaf(p, f, 6.9314718056e-1f);
    p = fmaf(p, f, 1.0f);
    return p * __int_as_float((e + 127) << 23);
}
__device__ __forceinline__ float frcp_(float x){   // x > 0
    float y = __int_as_float(0x7EF311C3 - __float_as_int(x));
    y = y * fmaf(-x, y, 2.0f);
    y = y * fmaf(-x, y, 2.0f);
    y = y * fmaf(-x, y, 2.0f);
    return y;
}
__device__ __forceinline__ float fsig_(float x){
    return frcp_(1.0f + fexp_(-x));
}
__device__ __forceinline__ float fsoftplus_(float x){
    float a = fabsf(x);
    float u = fexp_(-a);                       // (0, 1]
    float r = frcp_(u + 2.0f);
    float z = u * r;                           // z = u/(u+2) in (0, 1/3]
    float z2 = z * z;
    float p = 0.11111111f;                     // atanh series: ln(1+u) = 2*atanh(z)
    p = fmaf(p, z2, 0.14285714f);
    p = fmaf(p, z2, 0.2f);
    p = fmaf(p, z2, 0.33333333f);
    p = fmaf(p, z2, 1.0f);
    return fmaxf(x, 0.0f) + 2.0f * z * p;
}

// ---------------- index dtype detect + convert ------------------------------
__global__ void k_detect(const int* __restrict__ raw){
    __shared__ int s[256];
    int nz = 0;
    for (int i = threadIdx.x; i < 2048; i += 256) nz |= (raw[2*i+1] != 0);
    s[threadIdx.x] = nz;
    __syncthreads();
    for (int off = 128; off; off >>= 1){
        if (threadIdx.x < off) s[threadIdx.x] |= s[threadIdx.x + off];
        __syncthreads();
    }
    if (threadIdx.x == 0) g_flag = (s[0] == 0) ? 1 : 0;   // 1 => int64 source
}
__global__ void k_conv(const int* __restrict__ raw){
    int i = blockIdx.x * 256 + threadIdx.x;
    if (i < NR){
        int f = g_flag;
        g_idx[i] = raw[f ? (2*i) : i];    // single load, index selected (no OOB)
    }
}

// ---------------- embedding GEMM: atom = orig @ emb_W + b -------------------
__global__ void k_embed(const float* __restrict__ orig,
                        const float* __restrict__ W,
                        const float* __restrict__ B){
    extern __shared__ float sm[];
    float* Ws = sm;                 // 200*64
    float* As = sm + ORIGF*AFL;     // 32*200
    int t = threadIdx.x;
    for (int i = t; i < ORIGF*AFL; i += 256) Ws[i] = W[i];
    int r0 = blockIdx.x * 32;
    for (int i = t; i < 32*ORIGF; i += 256){
        int rr = i / ORIGF; int kk = i - rr*ORIGF; int row = r0 + rr;
        As[i] = (row < NA) ? orig[row*ORIGF + kk] : 0.0f;
    }
    __syncthreads();
    int c = t & 63, g = t >> 6;       // 4 row-groups x 64 cols
    float acc[8];
    #pragma unroll
    for (int r = 0; r < 8; r++) acc[r] = 0.0f;
    for (int k = 0; k < ORIGF; k++){
        float w = Ws[k*64 + c];
        #pragma unroll
        for (int r = 0; r < 8; r++)
            acc[r] = fmaf(As[(g*8+r)*ORIGF + k], w, acc[r]);
    }
    float bb = B[c];
    #pragma unroll
    for (int r = 0; r < 8; r++){
        int row = r0 + g*8 + r;
        if (row < NA) g_atom[row*64 + c] = acc[r] + bb;
    }
}

// ---------------- S = atom@W_self + b ; T = atom@W_nbr ----------------------
__global__ void k_st(const float* __restrict__ Wl, const float* __restrict__ bl){
    extern __shared__ float sm[];
    float* Ws = sm;            // 128*128 (rows 0..127 of msg W)
    float* As = sm + 16384;    // 32*64
    float* Bs = sm + 18432;    // 128
    int t = threadIdx.x;
    for (int i = t; i < 16384; i += 256) Ws[i] = Wl[i];
    int r0 = blockIdx.x * 32;
    for (int i = t; i < 2048; i += 256){
        int rr = i >> 6; int row = r0 + rr;
        As[i] = (row < NA) ? g_atom[row*64 + (i & 63)] : 0.0f;
    }
    if (t < 128) Bs[t] = bl[t];
    __syncthreads();
    int c = t & 127, h = t >> 7;      // h=0 -> S, h=1 -> T
    float acc[32];
    #pragma unroll
    for (int r = 0; r < 32; r++) acc[r] = 0.0f;
    const float* Wh = Ws + h*64*128;
    for (int k = 0; k < 64; k++){
        float w = Wh[k*128 + c];
        #pragma unroll
        for (int r = 0; r < 32; r++)
            acc[r] = fmaf(As[r*64 + k], w, acc[r]);
    }
    float bb = h ? 0.0f : Bs[c];
    float* dst = h ? g_T : g_S;
    #pragma unroll
    for (int r = 0; r < 32; r++){
        int row = r0 + r;
        if (row < NA) dst[row*128 + c] = acc[r] + bb;
    }
}

// ---------------- Z = nbr_fea@W_nf + S[n] + T[idx]; BN2 partial stats -------
__global__ void __launch_bounds__(256) k_msg(const float* __restrict__ Wl,
                                             const float* __restrict__ nbr){
    extern __shared__ float sm[];
    float* Wnf = sm;                  // 64*128
    float* NF  = sm + 8192;           // 48*64
    float* Ssm = sm + 11264;          // 4*128
    float* RS  = sm + 11776;          // 4*128
    float* RQ  = sm + 12288;          // 4*128
    int*   IDX = (int*)(sm + 12800);  // 48

    int t = threadIdx.x;
    int blk = blockIdx.x;
    int n0 = blk * 4;
    const float* Wsrc = Wl + 128*128;      // rows 128..191 (W_nf)
    for (int i = t; i < 8192; i += 256) Wnf[i] = Wsrc[i];
    const float* nsrc = nbr + (size_t)n0 * MN * NBRF;
    for (int i = t; i < 3072; i += 256) NF[i] = nsrc[i];
    for (int i = t; i < 512;  i += 256) Ssm[i] = g_S[n0*128 + i];
    if (t < 48) IDX[t] = g_idx[n0*MN + t];
    __syncthreads();

    int cp = (t & 63) << 1;
    int rg = t >> 6;                  // rg == local atom index (12 rows each)
    float ax[12], ay[12];
    #pragma unroll
    for (int r = 0; r < 12; r++){ ax[r] = 0.0f; ay[r] = 0.0f; }
    const float* NFr = NF + rg*12*64;
    for (int k = 0; k < 64; k++){
        float2 w = *(const float2*)(Wnf + k*128 + cp);
        #pragma unroll
        for (int r = 0; r < 12; r++){
            float a = NFr[r*64 + k];
            ax[r] = fmaf(a, w.x, ax[r]);
            ay[r] = fmaf(a, w.y, ay[r]);
        }
    }
    float Sx = Ssm[rg*128 + cp], Sy = Ssm[rg*128 + cp + 1];
    float ps = 0, pq = 0, ps2 = 0, pq2 = 0;
    #pragma unroll
    for (int r = 0; r < 12; r++){
        int li = rg*12 + r;
        int gi = IDX[li];
        float2 Tv = *(const float2*)(g_T + gi*128 + cp);
        float zx = ax[r] + Sx + Tv.x;
        float zy = ay[r] + Sy + Tv.y;
        float2 zz; zz.x = zx; zz.y = zy;
        *(float2*)(g_Z + (size_t)(n0*MN + li)*128 + cp) = zz;
        ps += zx;  pq  = fmaf(zx, zx, pq);
        ps2 += zy; pq2 = fmaf(zy, zy, pq2);
    }
    RS[rg*128 + cp] = ps;  RS[rg*128 + cp + 1] = ps2;
    RQ[rg*128 + cp] = pq;  RQ[rg*128 + cp + 1] = pq2;
    __syncthreads();
    if (t < 128){
        float s = RS[t] + RS[128+t] + RS[256+t] + RS[384+t];
        g_psum[blk*128 + t] = s;
    } else {
        int c2 = t - 128;
        float q = RQ[c2] + RQ[128+c2] + RQ[256+c2] + RQ[384+c2];
        g_psq[blk*128 + c2] = q;
    }
}

// ---------------- BN2 stat reduction (deterministic, 2 stages) --------------
__global__ void k_red2a(){
    int b = blockIdx.x, t = threadIdx.x;
    float s = 0, q = 0;
    for (int i = 0; i < 100; i++){
        int row = b*100 + i;
        s += g_psum[row*128 + t];
        q += g_psq [row*128 + t];
    }
    g_r2s[b*128 + t] = s; g_r2q[b*128 + t] = q;
}
__global__ void k_red2b(const float* __restrict__ g2, const float* __restrict__ b2){
    int t = threadIdx.x;
    float s = 0, q = 0;
    for (int i = 0; i < 125; i++){ s += g_r2s[i*128 + t]; q += g_r2q[i*128 + t]; }
    float inv  = 1.0f / 600000.0f;
    float mean = s * inv;
    float var  = fmaxf(q * inv - mean*mean, 0.0f);
    float rstd = rsqrtf(var + EPS);
    float A = g2[t] * rstd;
    g_A2[t] = A;
    g_B2[t] = b2[t] - mean * A;
}

// ---------------- BN2 apply + sigmoid*softplus + sum over M + BN1 partials --
__global__ void __launch_bounds__(128) k_gate(){
    __shared__ float comb[1024];           // [h][a][c]
    int t = threadIdx.x;
    int c = t & 63, h = t >> 6;
    int n0 = blockIdx.x * 8;
    float a2f = g_A2[c],      b2f = g_B2[c];
    float a2c = g_A2[64 + c], b2c = g_B2[64 + c];
    #pragma unroll 1
    for (int a = 0; a < 8; a++){
        int rbase = (n0 + a)*MN + h*6;
        float s = 0;
        #pragma unroll
        for (int mm = 0; mm < 6; mm++){
            const float* zr = g_Z + (size_t)(rbase + mm)*128;
            float f  = fmaf(zr[c],      a2f, b2f);
            float co = fmaf(zr[64 + c], a2c, b2c);
            s += fsig_(f) * fsoftplus_(co);
        }
        comb[h*512 + a*64 + c] = s;
    }
    __syncthreads();
    if (h == 0){
        float bs = 0, bq = 0;
        #pragma unroll
        for (int a = 0; a < 8; a++){
            float sv = comb[a*64 + c] + comb[512 + a*64 + c];
            g_summed[(n0 + a)*64 + c] = sv;
            bs += sv; bq = fmaf(sv, sv, bq);
        }
        g_p1s[blockIdx.x*64 + c] = bs;
        g_p1q[blockIdx.x*64 + c] = bq;
    }
}

// ---------------- BN1 stat reduction ----------------------------------------
__global__ void k_red1a(){
    int b = blockIdx.x, t = threadIdx.x;
    float s = 0, q = 0;
    for (int i = 0; i < 50; i++){
        int row = b*50 + i;
        s += g_p1s[row*64 + t];
        q += g_p1q[row*64 + t];
    }
    g_r1s[b*64 + t] = s; g_r1q[b*64 + t] = q;
}
__global__ void k_red1b(const float* __restrict__ g1, const float* __restrict__ b1){
    int t = threadIdx.x;
    float s = 0, q = 0;
    for (int i = 0; i < 125; i++){ s += g_r1s[i*64 + t]; q += g_r1q[i*64 + t]; }
    float inv  = 1.0f / (float)NA;
    float mean = s * inv;
    float var  = fmaxf(q * inv - mean*mean, 0.0f);
    float rstd = rsqrtf(var + EPS);
    float A = g1[t] * rstd;
    g_A1[t] = A;
    g_B1[t] = b1[t] - mean * A;
}

// ---------------- atom = softplus(atom + BN1(summed)) -----------------------
__global__ void k_update(){
    int i = blockIdx.x*256 + threadIdx.x;   // grid exact: 50000*64/256
    int c = i & 63;
    float v = g_atom[i] + fmaf(g_summed[i], g_A1[c], g_B1[c]);
    g_atom[i] = fsoftplus_(v);
}

// ---------------- pooling + head --------------------------------------------
__global__ void k_head(const float* __restrict__ fc1W, const float* __restrict__ fc1b,
                       const float* __restrict__ outW, const float* __restrict__ outb,
                       float* __restrict__ out){
    __shared__ float crys[128];
    __shared__ float red[128];
    int cid = blockIdx.x, t = threadIdx.x;
    if (t < 64){
        float v[10]; float s = 0;
        #pragma unroll
        for (int j = 0; j < 10; j++){ v[j] = g_atom[(cid*10 + j)*64 + t]; s += v[j]; }
        float mean = s * 0.1f;
        float q = 0;
        #pragma unroll
        for (int j = 0; j < 10; j++){ float d = v[j] - mean; q = fmaf(d, d, q); }
        float sd = sqrtf(q * (1.0f/9.0f));     // unbiased std
        crys[t]      = fsoftplus_(mean);
        crys[64 + t] = fsoftplus_(sd);
    }
    __syncthreads();
    float acc = fc1b[t];
    #pragma unroll 4
    for (int k = 0; k < 128; k++)
        acc = fmaf(crys[k], fc1W[k*128 + t], acc);
    float hv = fsoftplus_(acc);
    red[t] = hv * outW[t];
    __syncthreads();
    for (int off = 64; off; off >>= 1){
        if (t < off) red[t] += red[t + off];
        __syncthreads();
    }
    if (t == 0) out[cid] = red[0] + outb[0];
}

// ---------------- host ------------------------------------------------------
extern "C" void kernel_launch(void* const* d_in, const int* in_sizes, int n_in,
                              void* d_out, int out_size){
    const float* orig  = (const float*)d_in[0];
    const float* nbr   = (const float*)d_in[1];
    const int*   idxr  = (const int*)  d_in[2];
    // d_in[3] segment_ids: crystals are contiguous blocks of 10 atoms; unused
    const float* embW  = (const float*)d_in[4];
    const float* embB  = (const float*)d_in[5];
    const float* msgW  = (const float*)d_in[6];
    const float* msgB  = (const float*)d_in[7];
    const float* bn2g  = (const float*)d_in[8];
    const float* bn2b  = (const float*)d_in[9];
    const float* bn1g  = (const float*)d_in[10];
    const float* bn1b  = (const float*)d_in[11];
    const float* fc1W  = (const float*)d_in[12];
    const float* fc1b  = (const float*)d_in[13];
    const float* outW  = (const float*)d_in[14];
    const float* outb  = (const float*)d_in[15];
    float* out = (float*)d_out;

    const int SMEM_EMBED = (ORIGF*AFL + 32*ORIGF) * 4;     // 76800
    const int SMEM_ST    = (16384 + 2048 + 128) * 4;       // 74240
    const int SMEM_MSG   = 12800*4 + 48*4;                 // 51392
    cudaFuncSetAttribute(k_embed, cudaFuncAttributeMaxDynamicSharedMemorySize, SMEM_EMBED);
    cudaFuncSetAttribute(k_st,    cudaFuncAttributeMaxDynamicSharedMemorySize, SMEM_ST);
    cudaFuncSetAttribute(k_msg,   cudaFuncAttributeMaxDynamicSharedMemorySize, SMEM_MSG);

    k_detect<<<1, 256>>>(idxr);
    k_conv<<<(NR + 255)/256, 256>>>(idxr);
    k_embed<<<(NA + 31)/32, 256, SMEM_EMBED>>>(orig, embW, embB);

    for (int i = 0; i < 3; i++){
        const float* Wl = msgW + (size_t)i*192*128;
        const float* bl = msgB + i*128;
        k_st   <<<(NA + 31)/32, 256, SMEM_ST>>>(Wl, bl);
        k_msg  <<<NA/4, 256, SMEM_MSG>>>(Wl, nbr);
        k_red2a<<<125, 128>>>();
        k_red2b<<<1, 128>>>(bn2g + i*128, bn2b + i*128);
        k_gate <<<NA/8, 128>>>();
        k_red1a<<<125, 64>>>();
        k_red1b<<<1, 64>>>(bn1g + i*64, bn1b + i*64);
        k_update<<<NA*AFL/256, 256>>>();
    }
    k_head<<<NCRY, 128>>>(fc1W, fc1b, outW, outb, out);
}

// round 3
// speedup vs baseline: 1.3083x; 1.3083x over previous
#include <cuda_runtime.h>
#include <cuda_fp16.h>

#define NA 50000
#define MN 12
#define NR (NA*MN)          // 600000
#define NCRY 5000
#define ORIGF 200
#define AFL 64
#define EPS 1e-5f
#define MT 96               // k_msg row tile (8 atoms)
#define NBLK (NR/MT)        // 6250
#define GATOMS 16           // atoms per gate block
#define GBLK (NA/GATOMS)    // 3125

// ---------------- scratch ----------------------------------------------------
__device__ float g_atom[NA*AFL];
__device__ float g_S[NA*128];
__device__ float g_T[NA*128];
__device__ unsigned int g_Z2[(size_t)NR*64];   // half2(zf, zc) per (row, c)
__device__ float g_psum[NBLK*128];
__device__ float g_psq [NBLK*128];
__device__ float g_r2s[125*128];
__device__ float g_r2q[125*128];
__device__ float g_A2[128];
__device__ float g_B2[128];
__device__ float g_summed[NA*AFL];
__device__ float g_p1s[GBLK*64];
__device__ float g_p1q[GBLK*64];
__device__ float g_r1s[125*64];
__device__ float g_r1q[125*64];
__device__ float g_A1[64];
__device__ float g_B1[64];
__device__ int   g_idx[NR];
__device__ int   g_flag;

// ---------------- FMA-pipe transcendentals ----------------------------------
__device__ __forceinline__ float fexp_(float x){
    x = fminf(fmaxf(x, -87.0f), 87.0f);
    float t  = x * 1.4426950408889634f;
    float k  = t + 12582912.0f;
    float fi = k - 12582912.0f;
    float f  = t - fi;
    int   e  = __float_as_int(k) - 0x4B400000;
    float p  = 1.5403530393e-4f;
    p = fmaf(p, f, 1.3333558146e-3f);
    p = fmaf(p, f, 9.6181291918e-3f);
    p = fmaf(p, f, 5.5504108665e-2f);
    p = fmaf(p, f, 2.4022650696e-1f);
    p = fmaf(p, f, 6.9314718056e-1f);
    p = fmaf(p, f, 1.0f);
    return p * __int_as_float((e + 127) << 23);
}
__device__ __forceinline__ float frcp_(float x){   // x > 0, ~1e-7 rel err
    float y = __int_as_float(0x7EF311C3 - __float_as_int(x));
    y = y * fmaf(-x, y, 2.0f);
    y = y * fmaf(-x, y, 2.0f);
    return y;
}
__device__ __forceinline__ float fsig_(float x){
    return frcp_(1.0f + fexp_(-x));
}
__device__ __forceinline__ float fsoftplus_(float x){
    float a = fabsf(x);
    float u = fexp_(-a);
    float r = frcp_(u + 2.0f);
    float z = u * r;
    float z2 = z * z;
    float p = 0.11111111f;
    p = fmaf(p, z2, 0.14285714f);
    p = fmaf(p, z2, 0.2f);
    p = fmaf(p, z2, 0.33333333f);
    p = fmaf(p, z2, 1.0f);
    return fmaxf(x, 0.0f) + 2.0f * z * p;
}

// ---------------- tf32 mma helpers ------------------------------------------
__device__ __forceinline__ unsigned tf32r(float x){
    unsigned u; asm("cvt.rna.tf32.f32 %0, %1;" : "=r"(u) : "f"(x)); return u;
}
__device__ __forceinline__ void mma8(float& c0, float& c1, float& c2, float& c3,
                                     unsigned a0, unsigned a1, unsigned a2, unsigned a3,
                                     unsigned b0, unsigned b1){
    asm volatile("mma.sync.aligned.m16n8k8.row.col.f32.tf32.tf32.f32 "
        "{%0,%1,%2,%3}, {%4,%5,%6,%7}, {%8,%9}, {%0,%1,%2,%3};"
        : "+f"(c0), "+f"(c1), "+f"(c2), "+f"(c3)
        : "r"(a0), "r"(a1), "r"(a2), "r"(a3), "r"(b0), "r"(b1));
}

// ---------------- index dtype detect + convert ------------------------------
__global__ void k_detect(const int* __restrict__ raw){
    __shared__ int s[256];
    int nz = 0;
    for (int i = threadIdx.x; i < 2048; i += 256) nz |= (raw[2*i+1] != 0);
    s[threadIdx.x] = nz;
    __syncthreads();
    for (int off = 128; off; off >>= 1){
        if (threadIdx.x < off) s[threadIdx.x] |= s[threadIdx.x + off];
        __syncthreads();
    }
    if (threadIdx.x == 0) g_flag = (s[0] == 0) ? 1 : 0;
}
__global__ void k_conv(const int* __restrict__ raw){
    int i = blockIdx.x * 256 + threadIdx.x;
    if (i < NR){
        int f = g_flag;
        g_idx[i] = raw[f ? (2*i) : i];
    }
}

// ---------------- embedding GEMM (row-broadcast LDS tiling) -----------------
__global__ void __launch_bounds__(256) k_embed(const float* __restrict__ orig,
                                               const float* __restrict__ W,
                                               const float* __restrict__ B){
    extern __shared__ float sm[];
    float* As = sm;            // 128 x 200
    float* Ws = sm + 25600;    // 200 x 64
    int t = threadIdx.x;
    int r0 = blockIdx.x * 128;
    for (int i = t; i < 128*ORIGF; i += 256){
        int r = i / ORIGF, k = i - r*ORIGF;
        int row = r0 + r;
        As[i] = (row < NA) ? orig[(size_t)row*ORIGF + k] : 0.0f;
    }
    for (int i = t; i < ORIGF*64; i += 256) Ws[i] = W[i];
    __syncthreads();
    int cx = t & 31;               // cols 2cx, 2cx+1
    int ry = t >> 5;               // 8 groups x 16 rows
    float ax[16], ay[16];
    #pragma unroll
    for (int i = 0; i < 16; i++){ ax[i] = 0.0f; ay[i] = 0.0f; }
    const float* Arow = As + (ry*16)*ORIGF;
    for (int k = 0; k < ORIGF; k++){
        float2 w = *(const float2*)(Ws + k*64 + 2*cx);
        #pragma unroll
        for (int i = 0; i < 16; i++){
            float a = Arow[i*ORIGF + k];
            ax[i] = fmaf(a, w.x, ax[i]);
            ay[i] = fmaf(a, w.y, ay[i]);
        }
    }
    float2 bb = *(const float2*)(B + 2*cx);
    #pragma unroll
    for (int i = 0; i < 16; i++){
        int row = r0 + ry*16 + i;
        if (row < NA){
            float2 v; v.x = ax[i] + bb.x; v.y = ay[i] + bb.y;
            *(float2*)(g_atom + row*64 + 2*cx) = v;
        }
    }
}

// ---------------- S/T via tf32 mma: grid (391, 2) ---------------------------
__global__ void __launch_bounds__(256) k_st2(const float* __restrict__ Wl,
                                             const float* __restrict__ bl){
    extern __shared__ float sm[];
    float* As  = sm;            // 128 x 68 (k padded)
    float* WTs = sm + 8704;     // 128 x 68  (WT[n][k])
    float* Bs  = sm + 17408;    // 128
    int t = threadIdx.x;
    int lane = t & 31, warp = t >> 5;
    int gr = lane >> 2, q = lane & 3;
    int r0 = blockIdx.x * 128;
    int half = blockIdx.y;      // 0 -> S (+bias), 1 -> T

    for (int i = t; i < 128*64; i += 256){
        int r = i >> 6, k = i & 63;
        int row = r0 + r;
        As[r*68 + k] = (row < NA) ? __uint_as_float(tf32r(g_atom[row*64 + k])) : 0.0f;
    }
    const float* wsrc = Wl + half*64*128;
    for (int i = t; i < 64*128; i += 256){
        int k = i >> 7, n = i & 127;
        WTs[n*68 + k] = __uint_as_float(tf32r(wsrc[i]));
    }
    if (t < 128) Bs[t] = half ? 0.0f : bl[t];
    __syncthreads();

    float acc[16][4];
    #pragma unroll
    for (int j = 0; j < 16; j++){
        acc[j][0] = 0.0f; acc[j][1] = 0.0f; acc[j][2] = 0.0f; acc[j][3] = 0.0f;
    }
    int rb = warp * 16;
    for (int ks = 0; ks < 8; ks++){
        int k0 = ks*8 + q;
        unsigned a0 = __float_as_uint(As[(rb+gr)*68 + k0]);
        unsigned a1 = __float_as_uint(As[(rb+gr+8)*68 + k0]);
        unsigned a2 = __float_as_uint(As[(rb+gr)*68 + k0 + 4]);
        unsigned a3 = __float_as_uint(As[(rb+gr+8)*68 + k0 + 4]);
        #pragma unroll
        for (int j = 0; j < 16; j++){
            unsigned b0 = __float_as_uint(WTs[(j*8+gr)*68 + k0]);
            unsigned b1 = __float_as_uint(WTs[(j*8+gr)*68 + k0 + 4]);
            mma8(acc[j][0], acc[j][1], acc[j][2], acc[j][3], a0, a1, a2, a3, b0, b1);
        }
    }
    float* dst = half ? g_T : g_S;
    #pragma unroll
    for (int j = 0; j < 16; j++){
        int colb = j*8 + 2*q;
        float b0v = Bs[colb], b1v = Bs[colb+1];
        int row = r0 + rb + gr;
        if (row < NA){
            float2 v; v.x = acc[j][0] + b0v; v.y = acc[j][1] + b1v;
            *(float2*)(dst + row*128 + colb) = v;
        }
        row += 8;
        if (row < NA){
            float2 v; v.x = acc[j][2] + b0v; v.y = acc[j][3] + b1v;
            *(float2*)(dst + row*128 + colb) = v;
        }
    }
}

// ---------------- pass1: Z = nf@Wnf + S + T (tf32 mma), stats + half2 store -
__global__ void __launch_bounds__(192) k_msg(const float* __restrict__ Wl,
                                             const float* __restrict__ nbr){
    extern __shared__ float sm[];
    float* NFs = sm;                 // 96 x 68
    float* WTs = sm + 6528;          // 128 x 68 -> ends 15232
    float* Zs  = sm;                 // 96 x 132 = 12672 (aliases NFs/WTs)
    int*   rIdx= (int*)(sm + 15232); // 96
    float* ps  = sm + 15328;         // 3 x 128
    float* pq  = sm + 15712;         // 3 x 128

    int t = threadIdx.x;
    int lane = t & 31, warp = t >> 5;
    int gr = lane >> 2, q = lane & 3;
    int blk = blockIdx.x;
    int r0 = blk * MT;

    const float* nsrc = nbr + (size_t)r0 * 64;
    for (int i = t; i < MT*64; i += 192){
        int r = i >> 6, k = i & 63;
        NFs[r*68 + k] = __uint_as_float(tf32r(nsrc[i]));
    }
    const float* wsrc = Wl + 128*128;
    for (int i = t; i < 64*128; i += 192){
        int k = i >> 7, n = i & 127;
        WTs[n*68 + k] = __uint_as_float(tf32r(wsrc[i]));
    }
    for (int i = t; i < MT; i += 192) rIdx[i] = g_idx[r0 + i];
    __syncthreads();

    float acc[16][4];
    #pragma unroll
    for (int j = 0; j < 16; j++){
        acc[j][0] = 0.0f; acc[j][1] = 0.0f; acc[j][2] = 0.0f; acc[j][3] = 0.0f;
    }
    int rb = warp * 16;
    for (int ks = 0; ks < 8; ks++){
        int k0 = ks*8 + q;
        unsigned a0 = __float_as_uint(NFs[(rb+gr)*68 + k0]);
        unsigned a1 = __float_as_uint(NFs[(rb+gr+8)*68 + k0]);
        unsigned a2 = __float_as_uint(NFs[(rb+gr)*68 + k0 + 4]);
        unsigned a3 = __float_as_uint(NFs[(rb+gr+8)*68 + k0 + 4]);
        #pragma unroll
        for (int j = 0; j < 16; j++){
            unsigned b0 = __float_as_uint(WTs[(j*8+gr)*68 + k0]);
            unsigned b1 = __float_as_uint(WTs[(j*8+gr)*68 + k0 + 4]);
            mma8(acc[j][0], acc[j][1], acc[j][2], acc[j][3], a0, a1, a2, a3, b0, b1);
        }
    }
    __syncthreads();   // NFs/WTs dead; Zs takes over
    #pragma unroll
    for (int j = 0; j < 16; j++){
        int colb = j*8 + 2*q;
        float2 v0; v0.x = acc[j][0]; v0.y = acc[j][1];
        float2 v1; v1.x = acc[j][2]; v1.y = acc[j][3];
        *(float2*)(Zs + (rb+gr)*132 + colb)   = v0;
        *(float2*)(Zs + (rb+gr+8)*132 + colb) = v1;
    }
    __syncthreads();

    // column phase: z = Zs + S[atom] + T[idx]; stats + half2 store
    int c = t & 63, g = t >> 6;     // g in 0..2, 32 rows each
    float sf = 0, qf = 0, sc = 0, qc = 0;
    int abase = blk * 8;
    #pragma unroll 4
    for (int rr = 0; rr < 32; rr++){
        int r = g*32 + rr;
        int gi = rIdx[r];
        int sa = abase + r / 12;
        float zf = Zs[r*132 + c]      + g_S[sa*128 + c]      + g_T[gi*128 + c];
        float zc = Zs[r*132 + 64 + c] + g_S[sa*128 + 64 + c] + g_T[gi*128 + 64 + c];
        __half2 h = __floats2half2_rn(zf, zc);
        g_Z2[(size_t)(r0 + r)*64 + c] = *(unsigned*)&h;
        sf += zf; qf = fmaf(zf, zf, qf);
        sc += zc; qc = fmaf(zc, zc, qc);
    }
    ps[g*128 + c]      = sf;  ps[g*128 + 64 + c] = sc;
    pq[g*128 + c]      = qf;  pq[g*128 + 64 + c] = qc;
    __syncthreads();
    if (t < 128){
        float s = ps[t] + ps[128 + t] + ps[256 + t];
        float qv = pq[t] + pq[128 + t] + pq[256 + t];
        g_psum[blk*128 + t] = s;
        g_psq [blk*128 + t] = qv;
    }
}

// ---------------- BN2 stat reduction ----------------------------------------
__global__ void k_red2a(){
    int b = blockIdx.x, t = threadIdx.x;
    float s = 0, q = 0;
    for (int i = 0; i < 50; i++){
        int row = b*50 + i;
        s += g_psum[row*128 + t];
        q += g_psq [row*128 + t];
    }
    g_r2s[b*128 + t] = s; g_r2q[b*128 + t] = q;
}
__global__ void k_red2b(const float* __restrict__ g2, const float* __restrict__ b2){
    int t = threadIdx.x;
    float s = 0, q = 0;
    for (int i = 0; i < 125; i++){ s += g_r2s[i*128 + t]; q += g_r2q[i*128 + t]; }
    float inv  = 1.0f / 600000.0f;
    float mean = s * inv;
    float var  = fmaxf(q * inv - mean*mean, 0.0f);
    float rstd = rsqrtf(var + EPS);
    float A = g2[t] * rstd;
    g_A2[t] = A;
    g_B2[t] = b2[t] - mean * A;
}

// ---------------- gate: read half2 Z, BN2 + sig*softplus + sum over M -------
__global__ void __launch_bounds__(256) k_gate2(){
    __shared__ float pbs[4][64];
    __shared__ float pbq[4][64];
    int t = threadIdx.x;
    int c = t & 63, ag = t >> 6;   // 4 atom groups x 4 atoms
    int blk = blockIdx.x;
    float A2f = g_A2[c],      B2f = g_B2[c];
    float A2c = g_A2[64 + c], B2c = g_B2[64 + c];
    float bs = 0, bq = 0;
    #pragma unroll 1
    for (int a = 0; a < 4; a++){
        int atom = blk*GATOMS + ag*4 + a;
        const unsigned* zrow = g_Z2 + (size_t)atom*12*64 + c;
        float s = 0;
        #pragma unroll
        for (int m = 0; m < 12; m++){
            unsigned zz = zrow[m*64];
            __half2 h = *(__half2*)&zz;
            float zf = __low2float(h), zc = __high2float(h);
            float f  = fmaf(zf, A2f, B2f);
            float co = fmaf(zc, A2c, B2c);
            s += fsig_(f) * fsoftplus_(co);
        }
        g_summed[atom*64 + c] = s;
        bs += s; bq = fmaf(s, s, bq);
    }
    pbs[ag][c] = bs; pbq[ag][c] = bq;
    __syncthreads();
    if (t < 64){
        float s = pbs[0][t] + pbs[1][t] + pbs[2][t] + pbs[3][t];
        float q = pbq[0][t] + pbq[1][t] + pbq[2][t] + pbq[3][t];
        g_p1s[blk*64 + t] = s;
        g_p1q[blk*64 + t] = q;
    }
}

// ---------------- BN1 stat reduction ----------------------------------------
__global__ void k_red1a(){
    int b = blockIdx.x, t = threadIdx.x;
    float s = 0, q = 0;
    for (int i = 0; i < 25; i++){
        int row = b*25 + i;
        s += g_p1s[row*64 + t];
        q += g_p1q[row*64 + t];
    }
    g_r1s[b*64 + t] = s; g_r1q[b*64 + t] = q;
}
__global__ void k_red1b(const float* __restrict__ g1, const float* __restrict__ b1){
    int t = threadIdx.x;
    float s = 0, q = 0;
    for (int i = 0; i < 125; i++){ s += g_r1s[i*64 + t]; q += g_r1q[i*64 + t]; }
    float inv  = 1.0f / (float)NA;
    float mean = s * inv;
    float var  = fmaxf(q * inv - mean*mean, 0.0f);
    float rstd = rsqrtf(var + EPS);
    float A = g1[t] * rstd;
    g_A1[t] = A;
    g_B1[t] = b1[t] - mean * A;
}

// ---------------- atom = softplus(atom + BN1(summed)) -----------------------
__global__ void k_update(){
    int i = blockIdx.x*256 + threadIdx.x;
    int c = i & 63;
    float v = g_atom[i] + fmaf(g_summed[i], g_A1[c], g_B1[c]);
    g_atom[i] = fsoftplus_(v);
}

// ---------------- pooling + head --------------------------------------------
__global__ void k_head(const float* __restrict__ fc1W, const float* __restrict__ fc1b,
                       const float* __restrict__ outW, const float* __restrict__ outb,
                       float* __restrict__ out){
    __shared__ float crys[128];
    __shared__ float red[128];
    int cid = blockIdx.x, t = threadIdx.x;
    if (t < 64){
        float v[10]; float s = 0;
        #pragma unroll
        for (int j = 0; j < 10; j++){ v[j] = g_atom[(cid*10 + j)*64 + t]; s += v[j]; }
        float mean = s * 0.1f;
        float q = 0;
        #pragma unroll
        for (int j = 0; j < 10; j++){ float d = v[j] - mean; q = fmaf(d, d, q); }
        float sd = sqrtf(q * (1.0f/9.0f));
        crys[t]      = fsoftplus_(mean);
        crys[64 + t] = fsoftplus_(sd);
    }
    __syncthreads();
    float acc = fc1b[t];
    #pragma unroll 4
    for (int k = 0; k < 128; k++)
        acc = fmaf(crys[k], fc1W[k*128 + t], acc);
    float hv = fsoftplus_(acc);
    red[t] = hv * outW[t];
    __syncthreads();
    for (int off = 64; off; off >>= 1){
        if (t < off) red[t] += red[t + off];
        __syncthreads();
    }
    if (t == 0) out[cid] = red[0] + outb[0];
}

// ---------------- host ------------------------------------------------------
extern "C" void kernel_launch(void* const* d_in, const int* in_sizes, int n_in,
                              void* d_out, int out_size){
    const float* orig  = (const float*)d_in[0];
    const float* nbr   = (const float*)d_in[1];
    const int*   idxr  = (const int*)  d_in[2];
    const float* embW  = (const float*)d_in[4];
    const float* embB  = (const float*)d_in[5];
    const float* msgW  = (const float*)d_in[6];
    const float* msgB  = (const float*)d_in[7];
    const float* bn2g  = (const float*)d_in[8];
    const float* bn2b  = (const float*)d_in[9];
    const float* bn1g  = (const float*)d_in[10];
    const float* bn1b  = (const float*)d_in[11];
    const float* fc1W  = (const float*)d_in[12];
    const float* fc1b  = (const float*)d_in[13];
    const float* outW  = (const float*)d_in[14];
    const float* outb  = (const float*)d_in[15];
    float* out = (float*)d_out;

    const int SMEM_EMBED = (128*ORIGF + ORIGF*64) * 4;   // 153600
    const int SMEM_ST    = (8704 + 8704 + 128) * 4;      // 70144
    const int SMEM_MSG   = 16096 * 4;                    // 64384
    cudaFuncSetAttribute(k_embed, cudaFuncAttributeMaxDynamicSharedMemorySize, SMEM_EMBED);
    cudaFuncSetAttribute(k_st2,   cudaFuncAttributeMaxDynamicSharedMemorySize, SMEM_ST);
    cudaFuncSetAttribute(k_msg,   cudaFuncAttributeMaxDynamicSharedMemorySize, SMEM_MSG);

    k_detect<<<1, 256>>>(idxr);
    k_conv<<<(NR + 255)/256, 256>>>(idxr);
    k_embed<<<(NA + 127)/128, 256, SMEM_EMBED>>>(orig, embW, embB);

    for (int i = 0; i < 3; i++){
        const float* Wl = msgW + (size_t)i*192*128;
        const float* bl = msgB + i*128;
        k_st2  <<<dim3((NA + 127)/128, 2), 256, SMEM_ST>>>(Wl, bl);
        k_msg  <<<NBLK, 192, SMEM_MSG>>>(Wl, nbr);
        k_red2a<<<125, 128>>>();
        k_red2b<<<1, 128>>>(bn2g + i*128, bn2b + i*128);
        k_gate2<<<GBLK, 256>>>();
        k_red1a<<<125, 64>>>();
        k_red1b<<<1, 64>>>(bn1g + i*64, bn1b + i*64);
        k_update<<<NA*AFL/256, 256>>>();
    }
    k_head<<<NCRY, 128>>>(fc1W, fc1b, outW, outb, out);
}